// round 11
// baseline (speedup 1.0000x reference)
#include <cuda_runtime.h>
#include <cuda_fp16.h>
#include <stdint.h>
#include <string.h>

// Problem constants
#define PQ 400
#define PP 200000
#define NB 100
#define NCTA 148
#define NTH 544                          // 17 warps
#define NWPC 17
#define NWARP_TOT (NCTA * NWPC)          // 2516 warps chip-wide
#define ROW_F4 (PP / 4)                  // 50,000 float4 per row
#define TOT_F4 ((long long)PQ * ROW_F4)  // 20,000,000

typedef unsigned long long u64;
typedef unsigned int u32;

// Device scratch (no allocations allowed)
__device__ unsigned char d_lab8[PP];
__device__ float d_GN[NB * PQ];   // sum of (sel - 0.25(A+B)) = -(f1-f0) per (label,q)
__device__ float d_Pb[NB * PQ];   // sum of sigmoid per (label,q)
__device__ float d_Sel[PQ];       // sum of sel per q
__device__ int   d_cnt[NB];

// ---------------------------------------------------------------------------
// helpers
// ---------------------------------------------------------------------------
__device__ __forceinline__ u32 smem_u32(const void* p) {
    u32 a; asm("{ .reg .u64 t; cvta.to.shared.u64 t, %1; cvt.u32.u64 %0, t; }" : "=r"(a) : "l"(p));
    return a;
}
__device__ __forceinline__ u32 h2u(half2 h) {
    u32 r; memcpy(&r, &h, 4); return r;
}
__device__ __forceinline__ half2 u2h(u32 v) {
    half2 h; memcpy(&h, &v, 4); return h;
}

// byte-permute: build {g_i, p_i} interleavings
__device__ __forceinline__ u32 prmt(u32 a, u32 b, u32 sel) {
    u32 r; asm("prmt.b32 %0, %1, %2, %3;" : "=r"(r) : "r"(a), "r"(b), "r"(sel)); return r;
}

// Private-column bin RMW: LDS.32 + f16x2 add + STS.32 (no atomics, no races)
__device__ __forceinline__ void bin_rmw(u32 addr, u32 add) {
    u32 v;
    asm volatile("ld.shared.b32 %0, [%1];" : "=r"(v) : "r"(addr));
    asm("add.rn.f16x2 %0, %0, %1;" : "+r"(v) : "r"(add));
    asm volatile("st.shared.b32 [%0], %1;" :: "r"(addr), "r"(v) : "memory");
}

// Loop-invariant half2 constants
struct HK {
    half2 one, zero, negq;
    half2 e4, e3, e2, e1, e0;   // ln(1+e) deg-4 minimax in e on [0,1]
};
__device__ __forceinline__ HK make_consts() {
    HK K;
    K.one  = __float2half2_rn(1.0f);
    K.zero = __float2half2_rn(0.0f);
    K.negq = __float2half2_rn(-0.25f);
    K.e4 = __float2half2_rn(-5.4869696e-2f);
    K.e3 = __float2half2_rn( 2.16735288e-1f);
    K.e2 = __float2half2_rn(-4.64506268e-1f);
    K.e1 = __float2half2_rn( 9.9554191e-1f);
    K.e0 = __float2half2_rn( 6.9151e-5f);
    return K;
}

// ---------------------------------------------------------------------------
// pair2h: 2 elements (f32 in) -> f16x2 {g,p} bins; returns SEL half2
// ---------------------------------------------------------------------------
__device__ __forceinline__ half2 pair2h(float xlo, float xhi, const HK& K,
                                        u32& bin0, u32& bin1) {
    // exp argument computed in f32 (|x| is a free operand modifier on FMUL)
    float t0 = fabsf(xlo) * -1.4426950408889634f;
    float t1 = fabsf(xhi) * -1.4426950408889634f;
    half2 T  = __floats2half2_rn(t0, t1);
    half2 X  = __floats2half2_rn(xlo, xhi);
    half2 AX = __habs2(X);

    half2 E = h2exp2(T);                        // e = exp(-|x|)   (MUFU f16x2)
    half2 S = h2rcp(__hadd2(E, K.one));         // s = sigmoid(|x|) (MUFU f16x2)

    half2 L = __hfma2(E, K.e4, K.e3);           // L = log1p(e), Horner in e
    L = __hfma2(L, E, K.e2);
    L = __hfma2(L, E, K.e1);
    L = __hfma2(L, E, K.e0);

    half2 OS  = __hmul2(E, S);                  // sigmoid(-|x|)
    half2 AXL = __hadd2(AX, L);
    half2 A   = __hmul2(__hmul2(OS, OS), L);    // A = os^2 L
    half2 B   = __hmul2(__hmul2(S, S), AXL);    // B = s^2 (|x|+L)
    half2 AB  = __hadd2(A, B);

    half2 M   = __hlt2(X, K.zero);              // 1.0 where x<0
    half2 SEL = __hfma2(__hsub2(A, B), M, B);   // x<0 ? A : B
    half2 P   = __hfma2(__hsub2(OS, S), M, S);  // x<0 ? os : s
    half2 GN  = __hfma2(AB, K.negq, SEL);       // gneg = sel - 0.25(A+B)

    bin0 = prmt(h2u(GN), h2u(P), 0x5410);       // {g0, p0}
    bin1 = prmt(h2u(GN), h2u(P), 0x7632);       // {g1, p1}
    return SEL;
}

__device__ __forceinline__ void proc_f4(float4 x, u32 lb, u32 sb,
                                        const HK& K, float2& selacc) {
    u32 b0, b1, b2, b3;
    half2 s0 = pair2h(x.x, x.y, K, b0, b1);
    half2 s1 = pair2h(x.z, x.w, K, b2, b3);
    bin_rmw(sb + ( lb        & 0xFFu) * (NTH * 4u), b0);
    bin_rmw(sb + ((lb >>  8) & 0xFFu) * (NTH * 4u), b1);
    bin_rmw(sb + ((lb >> 16) & 0xFFu) * (NTH * 4u), b2);
    bin_rmw(sb + ( lb >> 24         ) * (NTH * 4u), b3);
    half2 sh = __hadd2(s0, s1);                 // values <= ~1.4, exact enough
    float2 sf = __half22float2(sh);
    selacc.x += sf.x; selacc.y += sf.y;
}

// ---------------------------------------------------------------------------
// Main kernel: flat warp ranges, thread-private f16x2 bin columns,
// depth-2 x 4-float4 software pipeline
// ---------------------------------------------------------------------------
__global__ __launch_bounds__(NTH, 1) void cost_kernel(const float* __restrict__ pm) {
    extern __shared__ u32 bins[];   // [NB][NTH] f16x2 {g,p}, column = tid (private)
    int tid = threadIdx.x, wid = tid >> 5, lane = tid & 31;

    #pragma unroll 4
    for (int j = 0; j < NB; j++) bins[j * NTH + tid] = 0u;
    // no __syncthreads needed: columns are strictly thread-private

    const HK K = make_consts();
    u32 sb = smem_u32(bins) + (u32)tid * 4u;

    u64 gw = (u64)blockIdx.x * NWPC + (u64)wid;
    long long beg = (long long)(gw * (u64)TOT_F4 / NWARP_TOT);
    long long end = (long long)((gw + 1) * (u64)TOT_F4 / NWARP_TOT);

    const u32* lv = reinterpret_cast<const u32*>(d_lab8);  // uchar4 per float4

    while (beg < end) {
        int row = (int)(beg / ROW_F4);
        long long rend = (long long)(row + 1) * ROW_F4;
        if (rend > end) rend = end;
        int c0 = (int)(beg - (long long)row * ROW_F4);
        int cn = (int)(rend - (long long)row * ROW_F4);

        const float4* xr = reinterpret_cast<const float4*>(pm + (size_t)row * PP);

        float2 selacc = make_float2(0.f, 0.f);
        int cL = c0 + lane;
        int nfull = (cn - c0) >> 7;      // full 128-f4 batches (4 f4/lane)

        float4 xb[2][4]; u32 lbv[2][4];

#define LOADB(b, cc) do {                                            \
            xb[b][0] = __ldcs(xr + (cc));                            \
            xb[b][1] = __ldcs(xr + (cc) + 32);                       \
            xb[b][2] = __ldcs(xr + (cc) + 64);                       \
            xb[b][3] = __ldcs(xr + (cc) + 96);                       \
            lbv[b][0] = lv[(cc)];        lbv[b][1] = lv[(cc) + 32];  \
            lbv[b][2] = lv[(cc) + 64];   lbv[b][3] = lv[(cc) + 96];  \
        } while (0)
#define PROCB(b) do {                                                \
            proc_f4(xb[b][0], lbv[b][0], sb, K, selacc);             \
            proc_f4(xb[b][1], lbv[b][1], sb, K, selacc);             \
            proc_f4(xb[b][2], lbv[b][2], sb, K, selacc);             \
            proc_f4(xb[b][3], lbv[b][3], sb, K, selacc);             \
        } while (0)

        if (nfull > 0) {
            LOADB(0, cL);
            for (int i = 1; i < nfull; i++) {
                int b = i & 1;
                LOADB(b, cL + (i << 7));
                PROCB(b ^ 1);
            }
            PROCB((nfull - 1) & 1);
            cL += nfull << 7;
        }
        for (; cL < cn; cL += 32)
            proc_f4(__ldcs(xr + cL), lv[cL], sb, K, selacc);

        // ---- segment flush (row uniform across warp) ----
        {
            float sv = selacc.x + selacc.y;
            #pragma unroll
            for (int o = 16; o; o >>= 1)
                sv += __shfl_xor_sync(0xFFFFFFFFu, sv, o);
            if (lane == 0) atomicAdd(&d_Sel[row], sv);

            for (int j = 0; j < NB; j++) {
                u32 v = bins[j * NTH + tid];
                bins[j * NTH + tid] = 0u;
                // 3 packed f16 reduce levels (16, 8, 4)
                u32 t;
                t = __shfl_xor_sync(0xFFFFFFFFu, v, 16);
                asm("add.rn.f16x2 %0, %0, %1;" : "+r"(v) : "r"(t));
                t = __shfl_xor_sync(0xFFFFFFFFu, v, 8);
                asm("add.rn.f16x2 %0, %0, %1;" : "+r"(v) : "r"(t));
                t = __shfl_xor_sync(0xFFFFFFFFu, v, 4);
                asm("add.rn.f16x2 %0, %0, %1;" : "+r"(v) : "r"(t));
                // unpack, finish in f32 (levels 2, 1)
                float2 gp = __half22float2(u2h(v));
                float g = gp.x, p = gp.y;
                #pragma unroll
                for (int o = 2; o; o >>= 1) {
                    g += __shfl_xor_sync(0xFFFFFFFFu, g, o);
                    p += __shfl_xor_sync(0xFFFFFFFFu, p, o);
                }
                if (lane == 0)  atomicAdd(&d_GN[j * PQ + row], g);
                if (lane == 16) atomicAdd(&d_Pb[j * PQ + row], p);
            }
        }
        beg = rend;
    }
#undef LOADB
#undef PROCB
}

// ---------------------------------------------------------------------------
// Zero d_cnt (must precede prep's atomics)
// ---------------------------------------------------------------------------
__global__ void zero_kernel() {
    if (threadIdx.x < NB) d_cnt[threadIdx.x] = 0;
}

// ---------------------------------------------------------------------------
// Prep: labels int32 -> uint8, histogram counts, zero accumulators
// ---------------------------------------------------------------------------
__global__ void prep_kernel(const int* __restrict__ labels) {
    __shared__ int h[NB];
    if (threadIdx.x < NB) h[threadIdx.x] = 0;
    __syncthreads();

    int i = blockIdx.x * blockDim.x + threadIdx.x;
    if (i < NB * PQ) { d_GN[i] = 0.f; d_Pb[i] = 0.f; }
    if (i < PQ) d_Sel[i] = 0.f;

    if (i < PP / 4) {
        int4 l4 = reinterpret_cast<const int4*>(labels)[i];
        uchar4 u;
        u.x = (unsigned char)l4.x; u.y = (unsigned char)l4.y;
        u.z = (unsigned char)l4.z; u.w = (unsigned char)l4.w;
        reinterpret_cast<uchar4*>(d_lab8)[i] = u;
        atomicAdd(&h[l4.x], 1);
        atomicAdd(&h[l4.y], 1);
        atomicAdd(&h[l4.z], 1);
        atomicAdd(&h[l4.w], 1);
    }
    __syncthreads();
    if (threadIdx.x < NB && h[threadIdx.x] != 0)
        atomicAdd(&d_cnt[threadIdx.x], h[threadIdx.x]);
}

// ---------------------------------------------------------------------------
// Finalize: out[q,j] = cost_mask + cost_dice
// ---------------------------------------------------------------------------
__global__ void finalize_kernel(float* __restrict__ out) {
    int q = blockIdx.x, j = threadIdx.x;   // 128 threads
    __shared__ float red[4];

    float pv = (j < NB) ? d_Pb[j * PQ + q] : 0.f;
    float w = pv;
    #pragma unroll
    for (int o = 16; o; o >>= 1)
        w += __shfl_xor_sync(0xFFFFFFFFu, w, o);
    if ((j & 31) == 0) red[j >> 5] = w;
    __syncthreads();
    float Psum = red[0] + red[1] + red[2] + red[3];

    if (j < NB) {
        float G   = -d_GN[j * PQ + q];
        float cm  = (G + 0.75f * d_Sel[q]) * (1.0f / (float)PP);
        float num = fmaf(2.0f, pv, 1.0f);
        float den = Psum + (float)d_cnt[j] + 1.0f;
        out[q * NB + j] = cm + 1.0f - num / den;
    }
}

// ---------------------------------------------------------------------------
extern "C" void kernel_launch(void* const* d_in, const int* in_sizes, int n_in,
                              void* d_out, int out_size) {
    const float* pm     = (const float*)d_in[0];
    const int*   labels = (const int*)d_in[1];
    (void)in_sizes; (void)n_in; (void)out_size;

    const int smem = NB * NTH * 4;  // 217,600 B (17 warps per SM)
    cudaFuncSetAttribute(cost_kernel, cudaFuncAttributeMaxDynamicSharedMemorySize, smem);

    zero_kernel<<<1, 128>>>();
    prep_kernel<<<(PP / 4 + 255) / 256, 256>>>(labels);
    cost_kernel<<<NCTA, NTH, smem>>>(pm);
    finalize_kernel<<<PQ, 128>>>((float*)d_out);
}

// round 12
// speedup vs baseline: 1.0506x; 1.0506x over previous
#include <cuda_runtime.h>
#include <stdint.h>

// Problem constants
#define PQ 400
#define PP 200000
#define NB 100
#define NCTA 148
#define NTH 576                          // 18 warps
#define NWPC 18
#define NWARP_TOT (NCTA * NWPC)          // 2664 warps chip-wide
#define ROW_F4 (PP / 4)                  // 50,000 float4 per row
#define TOT_F4 ((long long)PQ * ROW_F4)  // 20,000,000

typedef unsigned long long u64;
typedef unsigned int u32;

// Device scratch (no allocations allowed)
__device__ unsigned char d_lab8[PP];
__device__ float d_GN[NB * PQ];   // sum of (sel - 0.25(A+B)) = -(f1-f0) per (label,q)
__device__ float d_Pb[NB * PQ];   // sum of sigmoid per (label,q)
__device__ float d_Sel[PQ];       // sum of sel per q
__device__ int   d_cnt[NB];

// ---------------------------------------------------------------------------
// f32x2 / misc PTX helpers
// ---------------------------------------------------------------------------
#define FMA2(d, a, b, c) asm("fma.rn.f32x2 %0, %1, %2, %3;" : "=l"(d) : "l"(a), "l"(b), "l"(c))
#define MUL2(d, a, b)    asm("mul.rn.f32x2 %0, %1, %2;"     : "=l"(d) : "l"(a), "l"(b))
#define ADD2(d, a, b)    asm("add.rn.f32x2 %0, %1, %2;"     : "=l"(d) : "l"(a), "l"(b))
#define HADD2(d, a)      asm("add.rn.bf16x2 %0, %0, %1;"    : "+r"(d) : "r"(a))

__device__ __forceinline__ u64 pk2(float lo, float hi) {
    u64 r; asm("mov.b64 %0, {%1, %2};" : "=l"(r) : "f"(lo), "f"(hi)); return r;
}
__device__ __forceinline__ u64 bcast2(float v) {
    u64 r; asm("mov.b64 %0, {%1, %1};" : "=l"(r) : "f"(v)); return r;
}
__device__ __forceinline__ void upk2(u64 v, float& lo, float& hi) {
    asm("mov.b64 {%0, %1}, %2;" : "=f"(lo), "=f"(hi) : "l"(v));
}
__device__ __forceinline__ float ex2f(float x) {
    float r; asm("ex2.approx.ftz.f32 %0, %1;" : "=f"(r) : "f"(x)); return r;
}
__device__ __forceinline__ float rcpf(float x) {
    float r; asm("rcp.approx.ftz.f32 %0, %1;" : "=f"(r) : "f"(x)); return r;
}
__device__ __forceinline__ float slctf(float a, float b, float c) { // c>=0 ? a : b
    float d; asm("slct.f32.f32 %0, %1, %2, %3;" : "=f"(d) : "f"(a), "f"(b), "f"(c)); return d;
}
__device__ __forceinline__ u32 smem_u32(const void* p) {
    u32 a; asm("{ .reg .u64 t; cvta.to.shared.u64 t, %1; cvt.u32.u64 %0, t; }" : "=r"(a) : "l"(p));
    return a;
}
// pack {lo=g, hi=p} as bf16x2
__device__ __forceinline__ u32 cvt_gp(float g, float p) {
    u32 r; asm("cvt.rn.bf16x2.f32 %0, %1, %2;" : "=r"(r) : "f"(p), "f"(g)); return r;
}

// Private-column bin RMW: LDS.32 + packed bf16 add + STS.32 (no atomics, no races)
__device__ __forceinline__ void bin_rmw(u32 addr, u32 add) {
    u32 v;
    asm volatile("ld.shared.b32 %0, [%1];" : "=r"(v) : "r"(addr));
    asm("add.rn.bf16x2 %0, %0, %1;" : "+r"(v) : "r"(add));
    asm volatile("st.shared.b32 [%0], %1;" :: "r"(addr), "r"(v) : "memory");
}

// Loop-invariant packed constants
struct PkConsts {
    u64 one;
    u64 e4, e3, e2, e1, e0;   // ln(1+e) deg-4 minimax in e on [0,1]
    u64 negq;
};
__device__ __forceinline__ PkConsts make_consts() {
    PkConsts K;
    K.one  = bcast2(1.0f);
    K.e4 = bcast2(-5.4869696e-2f);
    K.e3 = bcast2( 2.16735288e-1f);
    K.e2 = bcast2(-4.64506268e-1f);
    K.e1 = bcast2( 9.9554191e-1f);
    K.e0 = bcast2( 6.9151e-5f);
    K.negq = bcast2(-0.25f);
    return K;
}

// ---------------------------------------------------------------------------
// pair2: 2 elements -> two bf16x2 {g,p} bin contributions; selacc += sel (f32x2)
// ---------------------------------------------------------------------------
__device__ __forceinline__ void pair2(float xlo, float xhi, const PkConsts& K,
                                      u32& bin0, u32& bin1, u64& selacc) {
    // scalar: |x| folds into FMUL as operand modifier
    float t0 = fabsf(xlo) * -1.4426950408889634f;
    float t1 = fabsf(xhi) * -1.4426950408889634f;
    u64 E = pk2(ex2f(t0), ex2f(t1));   // e = exp(-|x|)
    u64 EP1; ADD2(EP1, E, K.one);
    float q0, q1; upk2(EP1, q0, q1);
    u64 S = pk2(rcpf(q0), rcpf(q1));   // s = sigmoid(|x|)

    u64 L;                             // L = log1p(e), Horner in e (4 FMA2)
    FMA2(L, E, K.e4, K.e3);
    FMA2(L, L, E, K.e2);
    FMA2(L, L, E, K.e1);
    FMA2(L, L, E, K.e0);

    u64 AX = pk2(fabsf(xlo), fabsf(xhi));
    u64 OS;  MUL2(OS, E, S);           // sigmoid(-|x|)
    u64 AXL; ADD2(AXL, AX, L);
    u64 OS2; MUL2(OS2, OS, OS);
    u64 Apk; MUL2(Apk, OS2, L);        // A = os^2 * L
    u64 S2;  MUL2(S2, S, S);
    u64 Bpk; MUL2(Bpk, S2, AXL);       // B = s^2 * (|x|+L)
    u64 ABpk; ADD2(ABpk, Apk, Bpk);

    float a0, a1, b0, b1, os0, os1, s0, s1;
    upk2(Apk, a0, a1); upk2(Bpk, b0, b1);
    upk2(OS, os0, os1); upk2(S, s0, s1);

    float sel0 = slctf(b0, a0, xlo);   // x>=0 ? B : A
    float sel1 = slctf(b1, a1, xhi);
    float p0   = slctf(s0, os0, xlo);  // x>=0 ? s : os
    float p1   = slctf(s1, os1, xhi);

    u64 SEL = pk2(sel0, sel1);
    u64 GN;  FMA2(GN, ABpk, K.negq, SEL);   // gneg = sel - 0.25(A+B) = -(f1-f0)
    ADD2(selacc, selacc, SEL);

    float gn0, gn1; upk2(GN, gn0, gn1);
    bin0 = cvt_gp(gn0, p0);
    bin1 = cvt_gp(gn1, p1);
}

__device__ __forceinline__ void proc_f4(float4 x, u32 lb, u32 sb,
                                        const PkConsts& K, u64& selpk) {
    u32 b0, b1, b2, b3;
    pair2(x.x, x.y, K, b0, b1, selpk);
    pair2(x.z, x.w, K, b2, b3, selpk);
    bin_rmw(sb + ( lb        & 0xFFu) * (NTH * 4u), b0);
    bin_rmw(sb + ((lb >>  8) & 0xFFu) * (NTH * 4u), b1);
    bin_rmw(sb + ((lb >> 16) & 0xFFu) * (NTH * 4u), b2);
    bin_rmw(sb + ( lb >> 24         ) * (NTH * 4u), b3);
}

// ---------------------------------------------------------------------------
// Main kernel: flat warp ranges, thread-private bf16x2 bin columns,
// depth-2 x 4-float4 software pipeline (R7 structure, 18 warps)
// ---------------------------------------------------------------------------
__global__ __launch_bounds__(NTH, 1) void cost_kernel(const float* __restrict__ pm) {
    extern __shared__ u32 bins[];   // [NB][NTH] bf16x2 {g,p}, column = tid (private)
    int tid = threadIdx.x, wid = tid >> 5, lane = tid & 31;

    #pragma unroll 4
    for (int j = 0; j < NB; j++) bins[j * NTH + tid] = 0u;
    // no __syncthreads needed: columns are strictly thread-private

    const PkConsts K = make_consts();
    u32 sb = smem_u32(bins) + (u32)tid * 4u;

    u64 gw = (u64)blockIdx.x * NWPC + (u64)wid;
    long long beg = (long long)(gw * (u64)TOT_F4 / NWARP_TOT);
    long long end = (long long)((gw + 1) * (u64)TOT_F4 / NWARP_TOT);

    const u32* lv = reinterpret_cast<const u32*>(d_lab8);  // uchar4 per float4

    while (beg < end) {
        int row = (int)(beg / ROW_F4);
        long long rend = (long long)(row + 1) * ROW_F4;
        if (rend > end) rend = end;
        int c0 = (int)(beg - (long long)row * ROW_F4);
        int cn = (int)(rend - (long long)row * ROW_F4);

        const float4* xr = reinterpret_cast<const float4*>(pm + (size_t)row * PP);

        u64 selpk = 0ull;
        int cL = c0 + lane;
        int nfull = (cn - c0) >> 7;      // full 128-f4 batches (4 f4/lane)

        float4 xb[2][4]; u32 lbv[2][4];

#define LOADB(b, cc) do {                                            \
            xb[b][0] = __ldcs(xr + (cc));                            \
            xb[b][1] = __ldcs(xr + (cc) + 32);                       \
            xb[b][2] = __ldcs(xr + (cc) + 64);                       \
            xb[b][3] = __ldcs(xr + (cc) + 96);                       \
            lbv[b][0] = lv[(cc)];        lbv[b][1] = lv[(cc) + 32];  \
            lbv[b][2] = lv[(cc) + 64];   lbv[b][3] = lv[(cc) + 96];  \
        } while (0)
#define PROCB(b) do {                                                \
            proc_f4(xb[b][0], lbv[b][0], sb, K, selpk);              \
            proc_f4(xb[b][1], lbv[b][1], sb, K, selpk);              \
            proc_f4(xb[b][2], lbv[b][2], sb, K, selpk);              \
            proc_f4(xb[b][3], lbv[b][3], sb, K, selpk);              \
        } while (0)

        if (nfull > 0) {
            LOADB(0, cL);
            #pragma unroll 2
            for (int i = 1; i < nfull; i++) {
                int b = i & 1;
                LOADB(b, cL + (i << 7));
                PROCB(b ^ 1);
            }
            PROCB((nfull - 1) & 1);
            cL += nfull << 7;
        }
        for (; cL < cn; cL += 32)
            proc_f4(__ldcs(xr + cL), lv[cL], sb, K, selpk);

        // ---- segment flush (row uniform across warp) ----
        {
            float slo, shi; upk2(selpk, slo, shi);
            float sv = slo + shi;
            #pragma unroll
            for (int o = 16; o; o >>= 1)
                sv += __shfl_xor_sync(0xFFFFFFFFu, sv, o);
            if (lane == 0) atomicAdd(&d_Sel[row], sv);

            for (int j = 0; j < NB; j++) {
                u32 v = bins[j * NTH + tid];
                bins[j * NTH + tid] = 0u;
                // 3 packed bf16 reduce levels (16, 8, 4)
                u32 t;
                t = __shfl_xor_sync(0xFFFFFFFFu, v, 16); HADD2(v, t);
                t = __shfl_xor_sync(0xFFFFFFFFu, v, 8);  HADD2(v, t);
                t = __shfl_xor_sync(0xFFFFFFFFu, v, 4);  HADD2(v, t);
                // unpack, finish in f32 (levels 2, 1)
                float g = __uint_as_float(v << 16);
                float p = __uint_as_float(v & 0xFFFF0000u);
                #pragma unroll
                for (int o = 2; o; o >>= 1) {
                    g += __shfl_xor_sync(0xFFFFFFFFu, g, o);
                    p += __shfl_xor_sync(0xFFFFFFFFu, p, o);
                }
                if (lane == 0)  atomicAdd(&d_GN[j * PQ + row], g);
                if (lane == 16) atomicAdd(&d_Pb[j * PQ + row], p);
            }
        }
        beg = rend;
    }
#undef LOADB
#undef PROCB
}

// ---------------------------------------------------------------------------
// Zero d_cnt (must precede prep's atomics)
// ---------------------------------------------------------------------------
__global__ void zero_kernel() {
    if (threadIdx.x < NB) d_cnt[threadIdx.x] = 0;
}

// ---------------------------------------------------------------------------
// Prep: labels int32 -> uint8, histogram counts, zero accumulators
// ---------------------------------------------------------------------------
__global__ void prep_kernel(const int* __restrict__ labels) {
    __shared__ int h[NB];
    if (threadIdx.x < NB) h[threadIdx.x] = 0;
    __syncthreads();

    int i = blockIdx.x * blockDim.x + threadIdx.x;
    if (i < NB * PQ) { d_GN[i] = 0.f; d_Pb[i] = 0.f; }
    if (i < PQ) d_Sel[i] = 0.f;

    if (i < PP / 4) {
        int4 l4 = reinterpret_cast<const int4*>(labels)[i];
        uchar4 u;
        u.x = (unsigned char)l4.x; u.y = (unsigned char)l4.y;
        u.z = (unsigned char)l4.z; u.w = (unsigned char)l4.w;
        reinterpret_cast<uchar4*>(d_lab8)[i] = u;
        atomicAdd(&h[l4.x], 1);
        atomicAdd(&h[l4.y], 1);
        atomicAdd(&h[l4.z], 1);
        atomicAdd(&h[l4.w], 1);
    }
    __syncthreads();
    if (threadIdx.x < NB && h[threadIdx.x] != 0)
        atomicAdd(&d_cnt[threadIdx.x], h[threadIdx.x]);
}

// ---------------------------------------------------------------------------
// Finalize: out[q,j] = cost_mask + cost_dice
// ---------------------------------------------------------------------------
__global__ void finalize_kernel(float* __restrict__ out) {
    int q = blockIdx.x, j = threadIdx.x;   // 128 threads
    __shared__ float red[4];

    float pv = (j < NB) ? d_Pb[j * PQ + q] : 0.f;
    float w = pv;
    #pragma unroll
    for (int o = 16; o; o >>= 1)
        w += __shfl_xor_sync(0xFFFFFFFFu, w, o);
    if ((j & 31) == 0) red[j >> 5] = w;
    __syncthreads();
    float Psum = red[0] + red[1] + red[2] + red[3];

    if (j < NB) {
        float G   = -d_GN[j * PQ + q];
        float cm  = (G + 0.75f * d_Sel[q]) * (1.0f / (float)PP);
        float num = fmaf(2.0f, pv, 1.0f);
        float den = Psum + (float)d_cnt[j] + 1.0f;
        out[q * NB + j] = cm + 1.0f - num / den;
    }
}

// ---------------------------------------------------------------------------
extern "C" void kernel_launch(void* const* d_in, const int* in_sizes, int n_in,
                              void* d_out, int out_size) {
    const float* pm     = (const float*)d_in[0];
    const int*   labels = (const int*)d_in[1];
    (void)in_sizes; (void)n_in; (void)out_size;

    const int smem = NB * NTH * 4;  // 230,400 B (18 warps per SM)
    cudaFuncSetAttribute(cost_kernel, cudaFuncAttributeMaxDynamicSharedMemorySize, smem);

    zero_kernel<<<1, 128>>>();
    prep_kernel<<<(PP / 4 + 255) / 256, 256>>>(labels);
    cost_kernel<<<NCTA, NTH, smem>>>(pm);
    finalize_kernel<<<PQ, 128>>>((float*)d_out);
}

// round 13
// speedup vs baseline: 1.4169x; 1.3486x over previous
#include <cuda_runtime.h>
#include <stdint.h>

// Problem constants
#define PQ 400
#define PP 200000
#define NB 100
#define NCTA 148
#define NTH 512                          // 16 warps (128-reg budget for the pipeline)
#define NWPC 16
#define NWARP_TOT (NCTA * NWPC)          // 2368 warps chip-wide
#define ROW_F4 (PP / 4)                  // 50,000 float4 per row
#define TOT_F4 ((long long)PQ * ROW_F4)  // 20,000,000

typedef unsigned long long u64;
typedef unsigned int u32;

// Device scratch (no allocations allowed)
__device__ unsigned char d_lab8[PP];
__device__ float d_GN[NB * PQ];   // sum of (sel - 0.25(A+B)) = -(f1-f0) per (label,q)
__device__ float d_Pb[NB * PQ];   // sum of sigmoid per (label,q)
__device__ float d_Sel[PQ];       // sum of sel per q
__device__ int   d_cnt[NB];

// ---------------------------------------------------------------------------
// f32x2 / misc PTX helpers
// ---------------------------------------------------------------------------
#define FMA2(d, a, b, c) asm("fma.rn.f32x2 %0, %1, %2, %3;" : "=l"(d) : "l"(a), "l"(b), "l"(c))
#define MUL2(d, a, b)    asm("mul.rn.f32x2 %0, %1, %2;"     : "=l"(d) : "l"(a), "l"(b))
#define ADD2(d, a, b)    asm("add.rn.f32x2 %0, %1, %2;"     : "=l"(d) : "l"(a), "l"(b))
#define HADD2(d, a)      asm("add.rn.bf16x2 %0, %0, %1;"    : "+r"(d) : "r"(a))

__device__ __forceinline__ u64 pk2(float lo, float hi) {
    u64 r; asm("mov.b64 %0, {%1, %2};" : "=l"(r) : "f"(lo), "f"(hi)); return r;
}
__device__ __forceinline__ u64 bcast2(float v) {
    u64 r; asm("mov.b64 %0, {%1, %1};" : "=l"(r) : "f"(v)); return r;
}
__device__ __forceinline__ void upk2(u64 v, float& lo, float& hi) {
    asm("mov.b64 {%0, %1}, %2;" : "=f"(lo), "=f"(hi) : "l"(v));
}
__device__ __forceinline__ float ex2f(float x) {
    float r; asm("ex2.approx.ftz.f32 %0, %1;" : "=f"(r) : "f"(x)); return r;
}
__device__ __forceinline__ float rcpf(float x) {
    float r; asm("rcp.approx.ftz.f32 %0, %1;" : "=f"(r) : "f"(x)); return r;
}
__device__ __forceinline__ float slctf(float a, float b, float c) { // c>=0 ? a : b
    float d; asm("slct.f32.f32 %0, %1, %2, %3;" : "=f"(d) : "f"(a), "f"(b), "f"(c)); return d;
}
__device__ __forceinline__ u32 smem_u32(const void* p) {
    u32 a; asm("{ .reg .u64 t; cvta.to.shared.u64 t, %1; cvt.u32.u64 %0, t; }" : "=r"(a) : "l"(p));
    return a;
}
// pack {lo=g, hi=p} as bf16x2
__device__ __forceinline__ u32 cvt_gp(float g, float p) {
    u32 r; asm("cvt.rn.bf16x2.f32 %0, %1, %2;" : "=r"(r) : "f"(p), "f"(g)); return r;
}

// 4 guaranteed-independent bin RMWs: batched 4xLDS, 4xHADD2, 4xSTS
__device__ __forceinline__ void bin_rmw4(u32 a0, u32 a1, u32 a2, u32 a3,
                                         u32 b0, u32 b1, u32 b2, u32 b3) {
    u32 v0, v1, v2, v3;
    asm volatile("ld.shared.b32 %0, [%1];" : "=r"(v0) : "r"(a0));
    asm volatile("ld.shared.b32 %0, [%1];" : "=r"(v1) : "r"(a1));
    asm volatile("ld.shared.b32 %0, [%1];" : "=r"(v2) : "r"(a2));
    asm volatile("ld.shared.b32 %0, [%1];" : "=r"(v3) : "r"(a3));
    HADD2(v0, b0); HADD2(v1, b1); HADD2(v2, b2); HADD2(v3, b3);
    asm volatile("st.shared.b32 [%0], %1;" :: "r"(a0), "r"(v0) : "memory");
    asm volatile("st.shared.b32 [%0], %1;" :: "r"(a1), "r"(v1) : "memory");
    asm volatile("st.shared.b32 [%0], %1;" :: "r"(a2), "r"(v2) : "memory");
    asm volatile("st.shared.b32 [%0], %1;" :: "r"(a3), "r"(v3) : "memory");
}

// Loop-invariant packed constants
struct PkConsts {
    u64 one;
    u64 e4, e3, e2, e1, e0;   // ln(1+e) deg-4 minimax in e on [0,1]
    u64 negq;
};
__device__ __forceinline__ PkConsts make_consts() {
    PkConsts K;
    K.one  = bcast2(1.0f);
    K.e4 = bcast2(-5.4869696e-2f);
    K.e3 = bcast2( 2.16735288e-1f);
    K.e2 = bcast2(-4.64506268e-1f);
    K.e1 = bcast2( 9.9554191e-1f);
    K.e0 = bcast2( 6.9151e-5f);
    K.negq = bcast2(-0.25f);
    return K;
}

// ---------------------------------------------------------------------------
// pair2: 2 elements -> two bf16x2 {g,p} bin contributions; selacc += sel (f32x2)
// ---------------------------------------------------------------------------
__device__ __forceinline__ void pair2(float xlo, float xhi, const PkConsts& K,
                                      u32& bin0, u32& bin1, u64& selacc) {
    float t0 = fabsf(xlo) * -1.4426950408889634f;   // |x| free on FMUL
    float t1 = fabsf(xhi) * -1.4426950408889634f;
    u64 E = pk2(ex2f(t0), ex2f(t1));   // e = exp(-|x|)
    u64 EP1; ADD2(EP1, E, K.one);
    float q0, q1; upk2(EP1, q0, q1);
    u64 S = pk2(rcpf(q0), rcpf(q1));   // s = sigmoid(|x|)

    u64 L;                             // L = log1p(e), Horner in e (4 FMA2)
    FMA2(L, E, K.e4, K.e3);
    FMA2(L, L, E, K.e2);
    FMA2(L, L, E, K.e1);
    FMA2(L, L, E, K.e0);

    u64 AX = pk2(fabsf(xlo), fabsf(xhi));
    u64 OS;  MUL2(OS, E, S);           // sigmoid(-|x|)
    u64 AXL; ADD2(AXL, AX, L);
    u64 OS2; MUL2(OS2, OS, OS);
    u64 Apk; MUL2(Apk, OS2, L);        // A = os^2 * L
    u64 S2;  MUL2(S2, S, S);
    u64 Bpk; MUL2(Bpk, S2, AXL);       // B = s^2 * (|x|+L)
    u64 ABpk; ADD2(ABpk, Apk, Bpk);

    float a0, a1, b0, b1, os0, os1, s0, s1;
    upk2(Apk, a0, a1); upk2(Bpk, b0, b1);
    upk2(OS, os0, os1); upk2(S, s0, s1);

    float sel0 = slctf(b0, a0, xlo);   // x>=0 ? B : A
    float sel1 = slctf(b1, a1, xhi);
    float p0   = slctf(s0, os0, xlo);  // x>=0 ? s : os
    float p1   = slctf(s1, os1, xhi);

    u64 SEL = pk2(sel0, sel1);
    u64 GN;  FMA2(GN, ABpk, K.negq, SEL);   // gneg = sel - 0.25(A+B) = -(f1-f0)
    ADD2(selacc, selacc, SEL);

    float gn0, gn1; upk2(GN, gn0, gn1);
    bin0 = cvt_gp(gn0, p0);
    bin1 = cvt_gp(gn1, p1);
}

// sbk[k] = warp-base column address for element slot k (lane rotated by 8k)
__device__ __forceinline__ void proc_f4(float4 x, u32 lb, const u32* sbk,
                                        const PkConsts& K, u64& selpk) {
    u32 b0, b1, b2, b3;
    pair2(x.x, x.y, K, b0, b1, selpk);
    pair2(x.z, x.w, K, b2, b3, selpk);
    u32 a0 = sbk[0] + ( lb        & 0xFFu) * (NTH * 4u);
    u32 a1 = sbk[1] + ((lb >>  8) & 0xFFu) * (NTH * 4u);
    u32 a2 = sbk[2] + ((lb >> 16) & 0xFFu) * (NTH * 4u);
    u32 a3 = sbk[3] + ( lb >> 24         ) * (NTH * 4u);
    bin_rmw4(a0, a1, a2, a3, b0, b1, b2, b3);
}

// ---------------------------------------------------------------------------
// Main kernel: flat warp ranges, warp-private rotated bin columns,
// depth-2 x 4-float4 software pipeline (R7 champion structure)
// ---------------------------------------------------------------------------
__global__ __launch_bounds__(NTH, 1) void cost_kernel(const float* __restrict__ pm) {
    extern __shared__ u32 bins[];   // [NB][NTH] bf16x2 {g,p}
    int tid = threadIdx.x, wid = tid >> 5, lane = tid & 31;

    #pragma unroll 4
    for (int j = 0; j < NB; j++) bins[j * NTH + tid] = 0u;
    __syncwarp();   // lanes write each other's columns via rotation

    const PkConsts K = make_consts();
    u32 sb0 = smem_u32(bins);
    u32 sbk[4];
    #pragma unroll
    for (int k = 0; k < 4; k++)
        sbk[k] = sb0 + ((u32)(wid * 32) + (u32)((lane + 8 * k) & 31)) * 4u;

    u64 gw = (u64)blockIdx.x * NWPC + (u64)wid;
    long long beg = (long long)(gw * (u64)TOT_F4 / NWARP_TOT);
    long long end = (long long)((gw + 1) * (u64)TOT_F4 / NWARP_TOT);

    const u32* lv = reinterpret_cast<const u32*>(d_lab8);  // uchar4 per float4

    while (beg < end) {
        int row = (int)(beg / ROW_F4);
        long long rend = (long long)(row + 1) * ROW_F4;
        if (rend > end) rend = end;
        int c0 = (int)(beg - (long long)row * ROW_F4);
        int cn = (int)(rend - (long long)row * ROW_F4);

        const float4* xr = reinterpret_cast<const float4*>(pm + (size_t)row * PP);

        u64 selpk = 0ull;
        int cL = c0 + lane;
        int nfull = (cn - c0) >> 7;      // full 128-f4 batches (4 f4/lane)

        float4 xb[2][4]; u32 lbv[2][4];

#define LOADB(b, cc) do {                                            \
            xb[b][0] = __ldcs(xr + (cc));                            \
            xb[b][1] = __ldcs(xr + (cc) + 32);                       \
            xb[b][2] = __ldcs(xr + (cc) + 64);                       \
            xb[b][3] = __ldcs(xr + (cc) + 96);                       \
            lbv[b][0] = lv[(cc)];        lbv[b][1] = lv[(cc) + 32];  \
            lbv[b][2] = lv[(cc) + 64];   lbv[b][3] = lv[(cc) + 96];  \
        } while (0)
#define PROCB(b) do {                                                \
            proc_f4(xb[b][0], lbv[b][0], sbk, K, selpk);             \
            proc_f4(xb[b][1], lbv[b][1], sbk, K, selpk);             \
            proc_f4(xb[b][2], lbv[b][2], sbk, K, selpk);             \
            proc_f4(xb[b][3], lbv[b][3], sbk, K, selpk);             \
        } while (0)

        if (nfull > 0) {
            LOADB(0, cL);
            #pragma unroll 2
            for (int i = 1; i < nfull; i++) {
                int b = i & 1;
                LOADB(b, cL + (i << 7));
                PROCB(b ^ 1);
            }
            PROCB((nfull - 1) & 1);
            cL += nfull << 7;
        }
        for (; cL < cn; cL += 32)
            proc_f4(__ldcs(xr + cL), lv[cL], sbk, K, selpk);

        // ---- segment flush (row uniform across warp) ----
        {
            float slo, shi; upk2(selpk, slo, shi);
            float sv = slo + shi;
            #pragma unroll
            for (int o = 16; o; o >>= 1)
                sv += __shfl_xor_sync(0xFFFFFFFFu, sv, o);
            if (lane == 0) atomicAdd(&d_Sel[row], sv);

            __syncwarp();   // rotated writes must land before columns are read
            for (int j = 0; j < NB; j++) {
                u32 v = bins[j * NTH + tid];
                bins[j * NTH + tid] = 0u;
                // 3 packed bf16 reduce levels (16, 8, 4)
                u32 t;
                t = __shfl_xor_sync(0xFFFFFFFFu, v, 16); HADD2(v, t);
                t = __shfl_xor_sync(0xFFFFFFFFu, v, 8);  HADD2(v, t);
                t = __shfl_xor_sync(0xFFFFFFFFu, v, 4);  HADD2(v, t);
                // unpack, finish in f32 (levels 2, 1)
                float g = __uint_as_float(v << 16);
                float p = __uint_as_float(v & 0xFFFF0000u);
                #pragma unroll
                for (int o = 2; o; o >>= 1) {
                    g += __shfl_xor_sync(0xFFFFFFFFu, g, o);
                    p += __shfl_xor_sync(0xFFFFFFFFu, p, o);
                }
                if (lane == 0)  atomicAdd(&d_GN[j * PQ + row], g);
                if (lane == 16) atomicAdd(&d_Pb[j * PQ + row], p);
            }
            __syncwarp();   // zero-reset visible before next segment's writes
        }
        beg = rend;
    }
#undef LOADB
#undef PROCB
}

// ---------------------------------------------------------------------------
// Zero d_cnt (must precede prep's atomics)
// ---------------------------------------------------------------------------
__global__ void zero_kernel() {
    if (threadIdx.x < NB) d_cnt[threadIdx.x] = 0;
}

// ---------------------------------------------------------------------------
// Prep: labels int32 -> uint8, histogram counts, zero accumulators
// ---------------------------------------------------------------------------
__global__ void prep_kernel(const int* __restrict__ labels) {
    __shared__ int h[NB];
    if (threadIdx.x < NB) h[threadIdx.x] = 0;
    __syncthreads();

    int i = blockIdx.x * blockDim.x + threadIdx.x;
    if (i < NB * PQ) { d_GN[i] = 0.f; d_Pb[i] = 0.f; }
    if (i < PQ) d_Sel[i] = 0.f;

    if (i < PP / 4) {
        int4 l4 = reinterpret_cast<const int4*>(labels)[i];
        uchar4 u;
        u.x = (unsigned char)l4.x; u.y = (unsigned char)l4.y;
        u.z = (unsigned char)l4.z; u.w = (unsigned char)l4.w;
        reinterpret_cast<uchar4*>(d_lab8)[i] = u;
        atomicAdd(&h[l4.x], 1);
        atomicAdd(&h[l4.y], 1);
        atomicAdd(&h[l4.z], 1);
        atomicAdd(&h[l4.w], 1);
    }
    __syncthreads();
    if (threadIdx.x < NB && h[threadIdx.x] != 0)
        atomicAdd(&d_cnt[threadIdx.x], h[threadIdx.x]);
}

// ---------------------------------------------------------------------------
// Finalize: out[q,j] = cost_mask + cost_dice
// ---------------------------------------------------------------------------
__global__ void finalize_kernel(float* __restrict__ out) {
    int q = blockIdx.x, j = threadIdx.x;   // 128 threads
    __shared__ float red[4];

    float pv = (j < NB) ? d_Pb[j * PQ + q] : 0.f;
    float w = pv;
    #pragma unroll
    for (int o = 16; o; o >>= 1)
        w += __shfl_xor_sync(0xFFFFFFFFu, w, o);
    if ((j & 31) == 0) red[j >> 5] = w;
    __syncthreads();
    float Psum = red[0] + red[1] + red[2] + red[3];

    if (j < NB) {
        float G   = -d_GN[j * PQ + q];
        float cm  = (G + 0.75f * d_Sel[q]) * (1.0f / (float)PP);
        float num = fmaf(2.0f, pv, 1.0f);
        float den = Psum + (float)d_cnt[j] + 1.0f;
        out[q * NB + j] = cm + 1.0f - num / den;
    }
}

// ---------------------------------------------------------------------------
extern "C" void kernel_launch(void* const* d_in, const int* in_sizes, int n_in,
                              void* d_out, int out_size) {
    const float* pm     = (const float*)d_in[0];
    const int*   labels = (const int*)d_in[1];
    (void)in_sizes; (void)n_in; (void)out_size;

    const int smem = NB * NTH * 4;  // 204,800 B (16 warps per SM)
    cudaFuncSetAttribute(cost_kernel, cudaFuncAttributeMaxDynamicSharedMemorySize, smem);

    zero_kernel<<<1, 128>>>();
    prep_kernel<<<(PP / 4 + 255) / 256, 256>>>(labels);
    cost_kernel<<<NCTA, NTH, smem>>>(pm);
    finalize_kernel<<<PQ, 128>>>((float*)d_out);
}

// round 16
// speedup vs baseline: 1.9840x; 1.4003x over previous
#include <cuda_runtime.h>
#include <stdint.h>

// Problem constants
#define PQ 400
#define PP 200000
#define NB 100
#define NCTA 148
#define NTH 512                          // 16 warps (128-reg budget for the pipeline)
#define NWPC 16
#define NWARP_TOT (NCTA * NWPC)          // 2368 warps chip-wide
#define ROW_F4 (PP / 4)                  // 50,000 float4 per row
#define TOT_F4 ((long long)PQ * ROW_F4)  // 20,000,000

typedef unsigned long long u64;
typedef unsigned int u32;

// Device scratch (no allocations allowed)
__device__ unsigned char d_lab8[PP];
__device__ float d_GN[NB * PQ];   // sum of (sel - 0.25(A+B)) = -(f1-f0) per (label,q)
__device__ float d_Pb[NB * PQ];   // sum of sigmoid per (label,q)
__device__ float d_Sel[PQ];       // sum of sel per q
__device__ int   d_cnt[NB];

// ---------------------------------------------------------------------------
// f32x2 / misc PTX helpers
// ---------------------------------------------------------------------------
#define FMA2(d, a, b, c) asm("fma.rn.f32x2 %0, %1, %2, %3;" : "=l"(d) : "l"(a), "l"(b), "l"(c))
#define MUL2(d, a, b)    asm("mul.rn.f32x2 %0, %1, %2;"     : "=l"(d) : "l"(a), "l"(b))
#define ADD2(d, a, b)    asm("add.rn.f32x2 %0, %1, %2;"     : "=l"(d) : "l"(a), "l"(b))
#define HADD2(d, a)      asm("add.rn.bf16x2 %0, %0, %1;"    : "+r"(d) : "r"(a))

__device__ __forceinline__ u64 pk2(float lo, float hi) {
    u64 r; asm("mov.b64 %0, {%1, %2};" : "=l"(r) : "f"(lo), "f"(hi)); return r;
}
__device__ __forceinline__ u64 bcast2(float v) {
    u64 r; asm("mov.b64 %0, {%1, %1};" : "=l"(r) : "f"(v)); return r;
}
__device__ __forceinline__ void upk2(u64 v, float& lo, float& hi) {
    asm("mov.b64 {%0, %1}, %2;" : "=f"(lo), "=f"(hi) : "l"(v));
}
__device__ __forceinline__ float ex2f(float x) {
    float r; asm("ex2.approx.ftz.f32 %0, %1;" : "=f"(r) : "f"(x)); return r;
}
__device__ __forceinline__ float rcpf(float x) {
    float r; asm("rcp.approx.ftz.f32 %0, %1;" : "=f"(r) : "f"(x)); return r;
}
__device__ __forceinline__ float slctf(float a, float b, float c) { // c>=0 ? a : b
    float d; asm("slct.f32.f32 %0, %1, %2, %3;" : "=f"(d) : "f"(a), "f"(b), "f"(c)); return d;
}
__device__ __forceinline__ u32 smem_u32(const void* p) {
    u32 a; asm("{ .reg .u64 t; cvta.to.shared.u64 t, %1; cvt.u32.u64 %0, t; }" : "=r"(a) : "l"(p));
    return a;
}
// pack {lo=g, hi=p} as bf16x2
__device__ __forceinline__ u32 cvt_gp(float g, float p) {
    u32 r; asm("cvt.rn.bf16x2.f32 %0, %1, %2;" : "=r"(r) : "f"(p), "f"(g)); return r;
}

// 4 guaranteed-independent bin RMWs: batched 4xLDS, 4xHADD2, 4xSTS
__device__ __forceinline__ void bin_rmw4(u32 a0, u32 a1, u32 a2, u32 a3,
                                         u32 b0, u32 b1, u32 b2, u32 b3) {
    u32 v0, v1, v2, v3;
    asm volatile("ld.shared.b32 %0, [%1];" : "=r"(v0) : "r"(a0));
    asm volatile("ld.shared.b32 %0, [%1];" : "=r"(v1) : "r"(a1));
    asm volatile("ld.shared.b32 %0, [%1];" : "=r"(v2) : "r"(a2));
    asm volatile("ld.shared.b32 %0, [%1];" : "=r"(v3) : "r"(a3));
    HADD2(v0, b0); HADD2(v1, b1); HADD2(v2, b2); HADD2(v3, b3);
    asm volatile("st.shared.b32 [%0], %1;" :: "r"(a0), "r"(v0) : "memory");
    asm volatile("st.shared.b32 [%0], %1;" :: "r"(a1), "r"(v1) : "memory");
    asm volatile("st.shared.b32 [%0], %1;" :: "r"(a2), "r"(v2) : "memory");
    asm volatile("st.shared.b32 [%0], %1;" :: "r"(a3), "r"(v3) : "memory");
}

// Loop-invariant packed constants
struct PkConsts {
    u64 one;
    u64 e4, e3, e2, e1, e0;   // ln(1+e) deg-4 minimax in e on [0,1]
    u64 negq;
};
__device__ __forceinline__ PkConsts make_consts() {
    PkConsts K;
    K.one  = bcast2(1.0f);
    K.e4 = bcast2(-5.4869696e-2f);
    K.e3 = bcast2( 2.16735288e-1f);
    K.e2 = bcast2(-4.64506268e-1f);
    K.e1 = bcast2( 9.9554191e-1f);
    K.e0 = bcast2( 6.9151e-5f);
    K.negq = bcast2(-0.25f);
    return K;
}

// ---------------------------------------------------------------------------
// pair2: 2 elements -> two bf16x2 {g,p} bin contributions; selacc += sel (f32x2)
// ---------------------------------------------------------------------------
__device__ __forceinline__ void pair2(float xlo, float xhi, const PkConsts& K,
                                      u32& bin0, u32& bin1, u64& selacc) {
    float t0 = fabsf(xlo) * -1.4426950408889634f;   // |x| free on FMUL
    float t1 = fabsf(xhi) * -1.4426950408889634f;
    u64 E = pk2(ex2f(t0), ex2f(t1));   // e = exp(-|x|)
    u64 EP1; ADD2(EP1, E, K.one);
    float q0, q1; upk2(EP1, q0, q1);
    u64 S = pk2(rcpf(q0), rcpf(q1));   // s = sigmoid(|x|)

    u64 L;                             // L = log1p(e), Horner in e (4 FMA2)
    FMA2(L, E, K.e4, K.e3);
    FMA2(L, L, E, K.e2);
    FMA2(L, L, E, K.e1);
    FMA2(L, L, E, K.e0);

    u64 AX = pk2(fabsf(xlo), fabsf(xhi));
    u64 OS;  MUL2(OS, E, S);           // sigmoid(-|x|)
    u64 AXL; ADD2(AXL, AX, L);
    u64 OS2; MUL2(OS2, OS, OS);
    u64 Apk; MUL2(Apk, OS2, L);        // A = os^2 * L
    u64 S2;  MUL2(S2, S, S);
    u64 Bpk; MUL2(Bpk, S2, AXL);       // B = s^2 * (|x|+L)
    u64 ABpk; ADD2(ABpk, Apk, Bpk);

    float a0, a1, b0, b1, os0, os1, s0, s1;
    upk2(Apk, a0, a1); upk2(Bpk, b0, b1);
    upk2(OS, os0, os1); upk2(S, s0, s1);

    float sel0 = slctf(b0, a0, xlo);   // x>=0 ? B : A
    float sel1 = slctf(b1, a1, xhi);
    float p0   = slctf(s0, os0, xlo);  // x>=0 ? s : os
    float p1   = slctf(s1, os1, xhi);

    u64 SEL = pk2(sel0, sel1);
    u64 GN;  FMA2(GN, ABpk, K.negq, SEL);   // gneg = sel - 0.25(A+B) = -(f1-f0)
    ADD2(selacc, selacc, SEL);

    float gn0, gn1; upk2(GN, gn0, gn1);
    bin0 = cvt_gp(gn0, p0);
    bin1 = cvt_gp(gn1, p1);
}

// sbk[k] = warp-base column address for element slot k (lane rotated by 8k)
__device__ __forceinline__ void proc_f4(float4 x, u32 lb, const u32* sbk,
                                        const PkConsts& K, u64& selpk) {
    u32 b0, b1, b2, b3;
    pair2(x.x, x.y, K, b0, b1, selpk);
    pair2(x.z, x.w, K, b2, b3, selpk);
    u32 a0 = sbk[0] + ( lb        & 0xFFu) * (NTH * 4u);
    u32 a1 = sbk[1] + ((lb >>  8) & 0xFFu) * (NTH * 4u);
    u32 a2 = sbk[2] + ((lb >> 16) & 0xFFu) * (NTH * 4u);
    u32 a3 = sbk[3] + ( lb >> 24         ) * (NTH * 4u);
    bin_rmw4(a0, a1, a2, a3, b0, b1, b2, b3);
}

// ---------------------------------------------------------------------------
// Main kernel: flat warp ranges, warp-private rotated bin columns,
// depth-2 x 4-float4 software pipeline, lane-parallel transposed flush
// ---------------------------------------------------------------------------
__global__ __launch_bounds__(NTH, 1) void cost_kernel(const float* __restrict__ pm) {
    extern __shared__ u32 bins[];   // [NB][NTH] bf16x2 {g,p}
    int tid = threadIdx.x, wid = tid >> 5, lane = tid & 31;

    #pragma unroll 4
    for (int j = 0; j < NB; j++) bins[j * NTH + tid] = 0u;
    __syncwarp();   // lanes write each other's columns via rotation

    const PkConsts K = make_consts();
    u32 sb0 = smem_u32(bins);
    u32 sbk[4];
    #pragma unroll
    for (int k = 0; k < 4; k++)
        sbk[k] = sb0 + ((u32)(wid * 32) + (u32)((lane + 8 * k) & 31)) * 4u;

    u64 gw = (u64)blockIdx.x * NWPC + (u64)wid;
    long long beg = (long long)(gw * (u64)TOT_F4 / NWARP_TOT);
    long long end = (long long)((gw + 1) * (u64)TOT_F4 / NWARP_TOT);

    const u32* lv = reinterpret_cast<const u32*>(d_lab8);  // uchar4 per float4

    while (beg < end) {
        int row = (int)(beg / ROW_F4);
        long long rend = (long long)(row + 1) * ROW_F4;
        if (rend > end) rend = end;
        int c0 = (int)(beg - (long long)row * ROW_F4);
        int cn = (int)(rend - (long long)row * ROW_F4);

        const float4* xr = reinterpret_cast<const float4*>(pm + (size_t)row * PP);

        u64 selpk = 0ull;
        int cL = c0 + lane;
        int nfull = (cn - c0) >> 7;      // full 128-f4 batches (4 f4/lane)

        float4 xb[2][4]; u32 lbv[2][4];

#define LOADB(b, cc) do {                                            \
            xb[b][0] = __ldcs(xr + (cc));                            \
            xb[b][1] = __ldcs(xr + (cc) + 32);                       \
            xb[b][2] = __ldcs(xr + (cc) + 64);                       \
            xb[b][3] = __ldcs(xr + (cc) + 96);                       \
            lbv[b][0] = lv[(cc)];        lbv[b][1] = lv[(cc) + 32];  \
            lbv[b][2] = lv[(cc) + 64];   lbv[b][3] = lv[(cc) + 96];  \
        } while (0)
#define PROCB(b) do {                                                \
            proc_f4(xb[b][0], lbv[b][0], sbk, K, selpk);             \
            proc_f4(xb[b][1], lbv[b][1], sbk, K, selpk);             \
            proc_f4(xb[b][2], lbv[b][2], sbk, K, selpk);             \
            proc_f4(xb[b][3], lbv[b][3], sbk, K, selpk);             \
        } while (0)

        if (nfull > 0) {
            LOADB(0, cL);
            #pragma unroll 2
            for (int i = 1; i < nfull; i++) {
                int b = i & 1;
                LOADB(b, cL + (i << 7));
                PROCB(b ^ 1);
            }
            PROCB((nfull - 1) & 1);
            cL += nfull << 7;
        }
        for (; cL < cn; cL += 32)
            proc_f4(__ldcs(xr + cL), lv[cL], sbk, K, selpk);

        // ---- segment flush (row uniform across warp) ----
        {
            float slo, shi; upk2(selpk, slo, shi);
            float sv = slo + shi;
            #pragma unroll
            for (int o = 16; o; o >>= 1)
                sv += __shfl_xor_sync(0xFFFFFFFFu, sv, o);
            if (lane == 0) atomicAdd(&d_Sel[row], sv);

            __syncwarp();   // rotated writes must land before flush reads
            // Lane-parallel transposed flush: lane handles labels
            // {lane, lane+32, lane+64, lane+96}; reads its warp's 32-column
            // block via 8 k-rotated LDS.128 (conflict-free per 8-lane phase)
            u32 wbase = (u32)(wid * 32);
            #pragma unroll
            for (int gix = 0; gix < 4; gix++) {
                int j = lane + gix * 32;
                if (j < NB) {
                    u32 base = (u32)j * NTH + wbase;
                    uint4 vv[8];
                    #pragma unroll
                    for (int t = 0; t < 8; t++) {
                        int k = (t + lane) & 7;
                        vv[t] = *reinterpret_cast<uint4*>(&bins[base + (u32)(k << 2)]);
                    }
                    // within-load bf16 sums (values bounded ~25, bf16 safe)
                    float g = 0.f, p = 0.f;
                    #pragma unroll
                    for (int t = 0; t < 8; t++) {
                        u32 a = vv[t].x; HADD2(a, vv[t].y);
                        u32 b = vv[t].z; HADD2(b, vv[t].w);
                        HADD2(a, b);
                        g += __uint_as_float(a << 16);
                        p += __uint_as_float(a & 0xFFFF0000u);
                    }
                    atomicAdd(&d_GN[j * PQ + row], g);
                    atomicAdd(&d_Pb[j * PQ + row], p);
                    uint4 z = make_uint4(0u, 0u, 0u, 0u);
                    #pragma unroll
                    for (int t = 0; t < 8; t++) {
                        int k = (t + lane) & 7;
                        *reinterpret_cast<uint4*>(&bins[base + (u32)(k << 2)]) = z;
                    }
                }
            }
            __syncwarp();   // zero-reset visible before next segment's writes
        }
        beg = rend;
    }
#undef LOADB
#undef PROCB
}

// ---------------------------------------------------------------------------
// Zero d_cnt (must precede prep's atomics)
// ---------------------------------------------------------------------------
__global__ void zero_kernel() {
    if (threadIdx.x < NB) d_cnt[threadIdx.x] = 0;
}

// ---------------------------------------------------------------------------
// Prep: labels int32 -> uint8, histogram counts, zero accumulators
// ---------------------------------------------------------------------------
__global__ void prep_kernel(const int* __restrict__ labels) {
    __shared__ int h[NB];
    if (threadIdx.x < NB) h[threadIdx.x] = 0;
    __syncthreads();

    int i = blockIdx.x * blockDim.x + threadIdx.x;
    if (i < NB * PQ) { d_GN[i] = 0.f; d_Pb[i] = 0.f; }
    if (i < PQ) d_Sel[i] = 0.f;

    if (i < PP / 4) {
        int4 l4 = reinterpret_cast<const int4*>(labels)[i];
        uchar4 u;
        u.x = (unsigned char)l4.x; u.y = (unsigned char)l4.y;
        u.z = (unsigned char)l4.z; u.w = (unsigned char)l4.w;
        reinterpret_cast<uchar4*>(d_lab8)[i] = u;
        atomicAdd(&h[l4.x], 1);
        atomicAdd(&h[l4.y], 1);
        atomicAdd(&h[l4.z], 1);
        atomicAdd(&h[l4.w], 1);
    }
    __syncthreads();
    if (threadIdx.x < NB && h[threadIdx.x] != 0)
        atomicAdd(&d_cnt[threadIdx.x], h[threadIdx.x]);
}

// ---------------------------------------------------------------------------
// Finalize: out[q,j] = cost_mask + cost_dice
// ---------------------------------------------------------------------------
__global__ void finalize_kernel(float* __restrict__ out) {
    int q = blockIdx.x, j = threadIdx.x;   // 128 threads
    __shared__ float red[4];

    float pv = (j < NB) ? d_Pb[j * PQ + q] : 0.f;
    float w = pv;
    #pragma unroll
    for (int o = 16; o; o >>= 1)
        w += __shfl_xor_sync(0xFFFFFFFFu, w, o);
    if ((j & 31) == 0) red[j >> 5] = w;
    __syncthreads();
    float Psum = red[0] + red[1] + red[2] + red[3];

    if (j < NB) {
        float G   = -d_GN[j * PQ + q];
        float cm  = (G + 0.75f * d_Sel[q]) * (1.0f / (float)PP);
        float num = fmaf(2.0f, pv, 1.0f);
        float den = Psum + (float)d_cnt[j] + 1.0f;
        out[q * NB + j] = cm + 1.0f - num / den;
    }
}

// ---------------------------------------------------------------------------
extern "C" void kernel_launch(void* const* d_in, const int* in_sizes, int n_in,
                              void* d_out, int out_size) {
    const float* pm     = (const float*)d_in[0];
    const int*   labels = (const int*)d_in[1];
    (void)in_sizes; (void)n_in; (void)out_size;

    const int smem = NB * NTH * 4;  // 204,800 B (16 warps per SM)
    cudaFuncSetAttribute(cost_kernel, cudaFuncAttributeMaxDynamicSharedMemorySize, smem);

    zero_kernel<<<1, 128>>>();
    prep_kernel<<<(PP / 4 + 255) / 256, 256>>>(labels);
    cost_kernel<<<NCTA, NTH, smem>>>(pm);
    finalize_kernel<<<PQ, 128>>>((float*)d_out);
}